// round 6
// baseline (speedup 1.0000x reference)
#include <cuda_runtime.h>
#include <cuda_bf16.h>
#include <cstdint>
#include <math.h>

// ===================== problem constants =====================
constexpr int Bsz = 2;
constexpr int Hn  = 16;
constexpr int Sn  = 2048;
constexpr int Dh  = 128;

constexpr int BQ = 64;    // q rows per CTA (4 warps x 16 rows)
constexpr int BK = 32;    // k cols per iteration
constexpr int NT = 128;   // 4 warps

constexpr int RSB = 272;  // smem row stride in bytes (136 bf16) -> conflict-free ldmatrix

// smem byte offsets
constexpr int SM_QHI = 0;
constexpr int SM_QLO = SM_QHI + BQ * RSB;          // 17408
constexpr int SM_KHI = SM_QLO + BQ * RSB;          // 34816
constexpr int SM_KLO = SM_KHI + BK * RSB;          // 43520
constexpr int SM_VHI = SM_KLO + BK * RSB;          // 52224
constexpr int SM_VLO = SM_VHI + BK * RSB;          // 60928
constexpr int SM_AM  = SM_VLO + BK * RSB;          // 69632
constexpr int SM_TOTAL = SM_AM + BK * 4;           // 69760 B (x3 CTAs = 209.3KB/SM)

// ===================== helpers =====================
static __device__ __forceinline__ uint32_t smem_u32(const void* p) {
    uint32_t a;
    asm("{ .reg .u64 t; cvta.to.shared.u64 t, %1; cvt.u32.u64 %0, t; }" : "=r"(a) : "l"(p));
    return a;
}
static __device__ __forceinline__ void ldsm4(uint32_t* r, uint32_t a) {
    asm volatile("ldmatrix.sync.aligned.m8n8.x4.shared.b16 {%0,%1,%2,%3}, [%4];"
                 : "=r"(r[0]), "=r"(r[1]), "=r"(r[2]), "=r"(r[3]) : "r"(a));
}
static __device__ __forceinline__ void ldsm4t(uint32_t* r, uint32_t a) {
    asm volatile("ldmatrix.sync.aligned.m8n8.x4.trans.shared.b16 {%0,%1,%2,%3}, [%4];"
                 : "=r"(r[0]), "=r"(r[1]), "=r"(r[2]), "=r"(r[3]) : "r"(a));
}
static __device__ __forceinline__ void mma_bf16(float* c, const uint32_t* a, const uint32_t* b) {
    asm volatile("mma.sync.aligned.m16n8k16.row.col.f32.bf16.bf16.f32 "
                 "{%0,%1,%2,%3},{%4,%5,%6,%7},{%8,%9},{%0,%1,%2,%3};"
                 : "+f"(c[0]), "+f"(c[1]), "+f"(c[2]), "+f"(c[3])
                 : "r"(a[0]), "r"(a[1]), "r"(a[2]), "r"(a[3]), "r"(b[0]), "r"(b[1]));
}
// pack two f32 -> bf16x2 (first arg in low half)
static __device__ __forceinline__ uint32_t cvt2(float lo, float hi) {
    uint32_t r;
    asm("cvt.rn.bf16x2.f32 %0, %1, %2;" : "=r"(r) : "f"(hi), "f"(lo));
    return r;
}
static __device__ __forceinline__ float bflo(uint32_t u) { return __uint_as_float(u << 16); }
static __device__ __forceinline__ float bfhi(uint32_t u) { return __uint_as_float(u & 0xffff0000u); }
// MUFU exp2 (inputs pre-scaled to log2 domain)
static __device__ __forceinline__ float ex2f(float x) {
    float r;
    asm("ex2.approx.ftz.f32 %0, %1;" : "=f"(r) : "f"(x));
    return r;
}

constexpr float LOG2E = 1.4426950408889634f;

// load+split a (rows x 128) fp32 tile into bf16 hi/lo smem (16B STS chunks)
template <int ROWS, bool SCALE>
static __device__ __forceinline__ void load_tile(const float* __restrict__ g,
                                                 char* hib, char* lob, int tid) {
    #pragma unroll
    for (int it = 0; it < (ROWS * Dh / 8) / NT; ++it) {
        int e = it * NT + tid;                 // chunks of 8 floats
        int row = e >> 4, c8 = e & 15;
        const float4* src = reinterpret_cast<const float4*>(g) + 2 * e;
        float4 x = src[0], y = src[1];
        if (SCALE) {
            x.x *= LOG2E; x.y *= LOG2E; x.z *= LOG2E; x.w *= LOG2E;
            y.x *= LOG2E; y.y *= LOG2E; y.z *= LOG2E; y.w *= LOG2E;
        }
        uint32_t hx01 = cvt2(x.x, x.y), hx23 = cvt2(x.z, x.w);
        uint32_t hy01 = cvt2(y.x, y.y), hy23 = cvt2(y.z, y.w);
        uint32_t lx01 = cvt2(x.x - bflo(hx01), x.y - bfhi(hx01));
        uint32_t lx23 = cvt2(x.z - bflo(hx23), x.w - bfhi(hx23));
        uint32_t ly01 = cvt2(y.x - bflo(hy01), y.y - bfhi(hy01));
        uint32_t ly23 = cvt2(y.z - bflo(hy23), y.w - bfhi(hy23));
        int off = row * RSB + c8 * 16;
        *reinterpret_cast<uint4*>(hib + off) = make_uint4(hx01, hx23, hy01, hy23);
        *reinterpret_cast<uint4*>(lob + off) = make_uint4(lx01, lx23, ly01, ly23);
    }
}

// ===================== kernel =====================
__global__ __launch_bounds__(NT, 3)
void fa_mma_kernel(const float* __restrict__ q, const float* __restrict__ k,
                   const float* __restrict__ v, const float* __restrict__ am,
                   const float* __restrict__ hm, float* __restrict__ out)
{
    extern __shared__ char smem[];
    const uint32_t sbase = smem_u32(smem);
    float* am_s = reinterpret_cast<float*>(smem + SM_AM);

    const int tid = threadIdx.x, wid = tid >> 5, lane = tid & 31;
    const int bh = blockIdx.y, b = bh >> 4, h = bh & 15;
    const int qt = (int)gridDim.x - 1 - (int)blockIdx.x;   // heavy tiles first
    const int q0 = qt * BQ;
    const int nkt = 2 * (qt + 1);                          // BK = BQ/2

    const float* qg  = q + ((size_t)bh * Sn + q0) * Dh;
    const float* kg  = k + (size_t)bh * Sn * Dh;
    const float* vg  = v + (size_t)bh * Sn * Dh;
    const float* amg = am + (size_t)b * Sn;
    const float  hmv = hm[h];

    // ---- load Q tile (pre-scaled by log2e), split fp32 -> bf16 hi/lo ----
    load_tile<BQ, true>(qg, smem + SM_QHI, smem + SM_QLO, tid);

    // per-lane ldmatrix base addresses
    const int m0 = wid * 16;
    const uint32_t qoff = sbase + SM_QHI + (m0 + (lane & 15)) * RSB + ((lane >> 4) & 1) * 16;
    const uint32_t koff = sbase + SM_KHI + ((lane & 7) + ((lane >> 4) & 1) * 8) * RSB + ((lane >> 3) & 1) * 16;
    const uint32_t voff = sbase + SM_VHI + ((lane & 7) + ((lane >> 3) & 1) * 8) * RSB + ((lane >> 4) & 1) * 16;
    constexpr int DQL = SM_QLO - SM_QHI;
    constexpr int DKL = SM_KLO - SM_KHI;
    constexpr int DVL = SM_VLO - SM_VHI;

    float o[64];
    #pragma unroll
    for (int i = 0; i < 64; ++i) o[i] = 0.0f;
    float M0 = -INFINITY, M1 = -INFINITY, L0 = 0.0f, L1 = 0.0f;

    const int rg0 = q0 + m0 + (lane >> 2);   // global q row (upper)
    const int rg1 = rg0 + 8;
    const int c00 = 2 * (lane & 3);          // local col base within n8 tile

    for (int kt = 0; kt < nkt; ++kt) {
        __syncthreads();
        load_tile<BK, false>(kg + (size_t)kt * BK * Dh, smem + SM_KHI, smem + SM_KLO, tid);
        load_tile<BK, false>(vg + (size_t)kt * BK * Dh, smem + SM_VHI, smem + SM_VLO, tid);
        if (tid < BK) am_s[tid] = amg[kt * BK + tid] * LOG2E;
        __syncthreads();

        // ---- S' = log2e * Q K^T (3-pass split, 16x32 per warp) ----
        float sv[16];
        #pragma unroll
        for (int i = 0; i < 16; ++i) sv[i] = 0.0f;
        #pragma unroll
        for (int t = 0; t < 8; ++t) {                 // k16 tiles over d=128
            uint32_t ah[4], al[4];
            ldsm4(ah, qoff + t * 32);
            ldsm4(al, qoff + DQL + t * 32);
            #pragma unroll
            for (int g = 0; g < 2; ++g) {             // n16 groups over 32 cols
                uint32_t bh4[4], bl4[4];
                ldsm4(bh4, koff + g * (16 * RSB) + t * 32);
                ldsm4(bl4, koff + DKL + g * (16 * RSB) + t * 32);
                mma_bf16(sv + 8 * g,     ah, bh4);
                mma_bf16(sv + 8 * g,     ah, bl4);
                mma_bf16(sv + 8 * g,     al, bh4);
                mma_bf16(sv + 8 * g + 4, ah, bh4 + 2);
                mma_bf16(sv + 8 * g + 4, ah, bl4 + 2);
                mma_bf16(sv + 8 * g + 4, al, bh4 + 2);
            }
        }

        // ---- causal mask + additive attn_mask (log2 domain) ----
        float amr[8];
        #pragma unroll
        for (int n = 0; n < 4; ++n) {
            float2 a2 = *reinterpret_cast<const float2*>(&am_s[8 * n + c00]);
            amr[2 * n] = a2.x; amr[2 * n + 1] = a2.y;
        }
        if (kt >= nkt - 2) {   // last two k-tiles touch the diagonal
            #pragma unroll
            for (int n = 0; n < 4; ++n) {
                int cg = kt * BK + 8 * n + c00;
                sv[4*n+0] = (cg     <= rg0) ? sv[4*n+0] + amr[2*n]   : -1e30f;
                sv[4*n+1] = (cg + 1 <= rg0) ? sv[4*n+1] + amr[2*n+1] : -1e30f;
                sv[4*n+2] = (cg     <= rg1) ? sv[4*n+2] + amr[2*n]   : -1e30f;
                sv[4*n+3] = (cg + 1 <= rg1) ? sv[4*n+3] + amr[2*n+1] : -1e30f;
            }
        } else {
            #pragma unroll
            for (int n = 0; n < 4; ++n) {
                sv[4*n+0] += amr[2*n];   sv[4*n+1] += amr[2*n+1];
                sv[4*n+2] += amr[2*n];   sv[4*n+3] += amr[2*n+1];
            }
        }

        // ---- online softmax in base-2 domain (MUFU ex2) ----
        float t0 = -INFINITY, t1 = -INFINITY;
        #pragma unroll
        for (int n = 0; n < 4; ++n) {
            t0 = fmaxf(t0, fmaxf(sv[4*n+0], sv[4*n+1]));
            t1 = fmaxf(t1, fmaxf(sv[4*n+2], sv[4*n+3]));
        }
        t0 = fmaxf(t0, __shfl_xor_sync(0xffffffffu, t0, 1));
        t0 = fmaxf(t0, __shfl_xor_sync(0xffffffffu, t0, 2));
        t1 = fmaxf(t1, __shfl_xor_sync(0xffffffffu, t1, 1));
        t1 = fmaxf(t1, __shfl_xor_sync(0xffffffffu, t1, 2));
        float M0n = fmaxf(M0, t0), M1n = fmaxf(M1, t1);
        float a0 = ex2f(M0 - M0n), a1 = ex2f(M1 - M1n);
        M0 = M0n; M1 = M1n;

        float l0 = 0.0f, l1 = 0.0f;
        #pragma unroll
        for (int n = 0; n < 4; ++n) {
            sv[4*n+0] = ex2f(sv[4*n+0] - M0n);
            sv[4*n+1] = ex2f(sv[4*n+1] - M0n);
            l0 += sv[4*n+0] + sv[4*n+1];
            sv[4*n+2] = ex2f(sv[4*n+2] - M1n);
            sv[4*n+3] = ex2f(sv[4*n+3] - M1n);
            l1 += sv[4*n+2] + sv[4*n+3];
        }
        l0 += __shfl_xor_sync(0xffffffffu, l0, 1);
        l0 += __shfl_xor_sync(0xffffffffu, l0, 2);
        l1 += __shfl_xor_sync(0xffffffffu, l1, 1);
        l1 += __shfl_xor_sync(0xffffffffu, l1, 2);
        L0 = L0 * a0 + l0;
        L1 = L1 * a1 + l1;
        #pragma unroll
        for (int n = 0; n < 16; ++n) {
            o[4*n+0] *= a0; o[4*n+1] *= a0;
            o[4*n+2] *= a1; o[4*n+3] *= a1;
        }

        // ---- P -> bf16 hi/lo A-fragments ----
        uint32_t ph[2][4], pl[2][4];
        #pragma unroll
        for (int t = 0; t < 2; ++t) {
            #pragma unroll
            for (int rix = 0; rix < 4; ++rix) {
                float f0 = sv[8*t + 2*rix], f1 = sv[8*t + 2*rix + 1];
                uint32_t hh = cvt2(f0, f1);
                ph[t][rix] = hh;
                pl[t][rix] = cvt2(f0 - bflo(hh), f1 - bfhi(hh));
            }
        }

        // ---- O += P V (3-pass split, 16x128 per warp) ----
        #pragma unroll
        for (int t = 0; t < 2; ++t) {                 // k16 tiles over BK=32
            #pragma unroll
            for (int g = 0; g < 8; ++g) {             // n16 groups over d=128
                uint32_t vh4[4], vl4[4];
                ldsm4t(vh4, voff + t * (16 * RSB) + g * 32);
                ldsm4t(vl4, voff + DVL + t * (16 * RSB) + g * 32);
                mma_bf16(o + 8 * g,     ph[t], vh4);
                mma_bf16(o + 8 * g,     ph[t], vl4);
                mma_bf16(o + 8 * g,     pl[t], vh4);
                mma_bf16(o + 8 * g + 4, ph[t], vh4 + 2);
                mma_bf16(o + 8 * g + 4, ph[t], vl4 + 2);
                mma_bf16(o + 8 * g + 4, pl[t], vh4 + 2);
            }
        }
    }

    // ---- epilogue: normalize, head_mask, store ----
    float li0 = hmv / L0, li1 = hmv / L1;
    float* o0 = out + ((size_t)bh * Sn + rg0) * Dh;
    float* o1 = o0 + 8 * Dh;
    #pragma unroll
    for (int n = 0; n < 16; ++n) {
        int c = 8 * n + c00;
        *reinterpret_cast<float2*>(o0 + c) = make_float2(o[4*n+0] * li0, o[4*n+1] * li0);
        *reinterpret_cast<float2*>(o1 + c) = make_float2(o[4*n+2] * li1, o[4*n+3] * li1);
    }
}

// ===================== launch =====================
extern "C" void kernel_launch(void* const* d_in, const int* in_sizes, int n_in,
                              void* d_out, int out_size)
{
    const float* q  = (const float*)d_in[0];
    const float* k  = (const float*)d_in[1];
    const float* v  = (const float*)d_in[2];
    const float* am = (const float*)d_in[3];
    const float* hm = (const float*)d_in[4];
    float* out = (float*)d_out;

    cudaFuncSetAttribute(fa_mma_kernel,
                         cudaFuncAttributeMaxDynamicSharedMemorySize, SM_TOTAL);

    dim3 grid(Sn / BQ, Bsz * Hn);   // (32 q-tiles, 32 bh)
    fa_mma_kernel<<<grid, NT, SM_TOTAL>>>(q, k, v, am, hm, out);
}

// round 7
// speedup vs baseline: 1.2557x; 1.2557x over previous
#include <cuda_runtime.h>
#include <cuda_fp16.h>
#include <cstdint>
#include <math.h>

// ===================== problem constants =====================
constexpr int Bsz = 2;
constexpr int Hn  = 16;
constexpr int Sn  = 2048;
constexpr int Dh  = 128;

constexpr int BQ = 64;    // q rows per CTA (4 warps x 16 rows)
constexpr int BK = 64;    // k cols per iteration
constexpr int NT = 128;   // 4 warps

constexpr int RSB = 272;  // smem row stride in bytes (136 fp16) -> conflict-free ldmatrix

// smem byte offsets: Q hi-only; K,V hi+lo
constexpr int SM_QHI = 0;
constexpr int SM_KHI = SM_QHI + BQ * RSB;          // 17408
constexpr int SM_KLO = SM_KHI + BK * RSB;          // 34816
constexpr int SM_VHI = SM_KLO + BK * RSB;          // 52224
constexpr int SM_VLO = SM_VHI + BK * RSB;          // 69632
constexpr int SM_AM  = SM_VLO + BK * RSB;          // 87040
constexpr int SM_TOTAL = SM_AM + BK * 4;           // 87296 B (x2 CTAs = 174.6KB/SM)

// ===================== helpers =====================
static __device__ __forceinline__ uint32_t smem_u32(const void* p) {
    uint32_t a;
    asm("{ .reg .u64 t; cvta.to.shared.u64 t, %1; cvt.u32.u64 %0, t; }" : "=r"(a) : "l"(p));
    return a;
}
static __device__ __forceinline__ void ldsm4(uint32_t* r, uint32_t a) {
    asm volatile("ldmatrix.sync.aligned.m8n8.x4.shared.b16 {%0,%1,%2,%3}, [%4];"
                 : "=r"(r[0]), "=r"(r[1]), "=r"(r[2]), "=r"(r[3]) : "r"(a));
}
static __device__ __forceinline__ void ldsm4t(uint32_t* r, uint32_t a) {
    asm volatile("ldmatrix.sync.aligned.m8n8.x4.trans.shared.b16 {%0,%1,%2,%3}, [%4];"
                 : "=r"(r[0]), "=r"(r[1]), "=r"(r[2]), "=r"(r[3]) : "r"(a));
}
static __device__ __forceinline__ void mma_f16(float* c, const uint32_t* a, const uint32_t* b) {
    asm volatile("mma.sync.aligned.m16n8k16.row.col.f32.f16.f16.f32 "
                 "{%0,%1,%2,%3},{%4,%5,%6,%7},{%8,%9},{%0,%1,%2,%3};"
                 : "+f"(c[0]), "+f"(c[1]), "+f"(c[2]), "+f"(c[3])
                 : "r"(a[0]), "r"(a[1]), "r"(a[2]), "r"(a[3]), "r"(b[0]), "r"(b[1]));
}
// pack two f32 -> f16x2 (first arg in low half)
static __device__ __forceinline__ uint32_t cvt2h(float lo, float hi) {
    uint32_t r;
    asm("cvt.rn.f16x2.f32 %0, %1, %2;" : "=r"(r) : "f"(hi), "f"(lo));
    return r;
}
static __device__ __forceinline__ float2 h2f2(uint32_t u) {
    __half2 h = *reinterpret_cast<__half2*>(&u);
    return __half22float2(h);
}
// MUFU exp2 (inputs pre-scaled to log2 domain)
static __device__ __forceinline__ float ex2f(float x) {
    float r;
    asm("ex2.approx.ftz.f32 %0, %1;" : "=f"(r) : "f"(x));
    return r;
}

constexpr float LOG2E = 1.4426950408889634f;

// load 64x128 fp32 tile -> fp16 hi + lo smem tiles (compensated pair)
static __device__ __forceinline__ void load_split(const float* __restrict__ g,
                                                  char* hib, char* lob, int tid) {
    #pragma unroll
    for (int it = 0; it < 8; ++it) {
        int e = it * NT + tid;                 // 1024 chunks of 8 floats
        int row = e >> 4, c8 = e & 15;
        const float4* src = reinterpret_cast<const float4*>(g) + 2 * e;
        float4 x = src[0], y = src[1];
        uint32_t h0 = cvt2h(x.x, x.y), h1 = cvt2h(x.z, x.w);
        uint32_t h2 = cvt2h(y.x, y.y), h3 = cvt2h(y.z, y.w);
        float2 f0 = h2f2(h0), f1 = h2f2(h1), f2 = h2f2(h2), f3 = h2f2(h3);
        uint32_t l0 = cvt2h(x.x - f0.x, x.y - f0.y);
        uint32_t l1 = cvt2h(x.z - f1.x, x.w - f1.y);
        uint32_t l2 = cvt2h(y.x - f2.x, y.y - f2.y);
        uint32_t l3 = cvt2h(y.z - f3.x, y.w - f3.y);
        int off = row * RSB + c8 * 16;
        *reinterpret_cast<uint4*>(hib + off) = make_uint4(h0, h1, h2, h3);
        *reinterpret_cast<uint4*>(lob + off) = make_uint4(l0, l1, l2, l3);
    }
}
// load 64x128 fp32 tile -> fp16 hi only, scaled by log2e (Q)
static __device__ __forceinline__ void load_hi_scaled(const float* __restrict__ g,
                                                      char* hib, int tid) {
    #pragma unroll
    for (int it = 0; it < 8; ++it) {
        int e = it * NT + tid;
        int row = e >> 4, c8 = e & 15;
        const float4* src = reinterpret_cast<const float4*>(g) + 2 * e;
        float4 x = src[0], y = src[1];
        uint32_t h0 = cvt2h(x.x * LOG2E, x.y * LOG2E), h1 = cvt2h(x.z * LOG2E, x.w * LOG2E);
        uint32_t h2 = cvt2h(y.x * LOG2E, y.y * LOG2E), h3 = cvt2h(y.z * LOG2E, y.w * LOG2E);
        int off = row * RSB + c8 * 16;
        *reinterpret_cast<uint4*>(hib + off) = make_uint4(h0, h1, h2, h3);
    }
}

// ===================== kernel =====================
__global__ __launch_bounds__(NT, 2)
void fa_mma_kernel(const float* __restrict__ q, const float* __restrict__ k,
                   const float* __restrict__ v, const float* __restrict__ am,
                   const float* __restrict__ hm, float* __restrict__ out)
{
    extern __shared__ char smem[];
    const uint32_t sbase = smem_u32(smem);
    float* am_s = reinterpret_cast<float*>(smem + SM_AM);

    const int tid = threadIdx.x, wid = tid >> 5, lane = tid & 31;
    const int bh = blockIdx.y, b = bh >> 4, h = bh & 15;
    const int qt = (int)gridDim.x - 1 - (int)blockIdx.x;   // heavy tiles first
    const int q0 = qt * BQ;
    const int nkt = qt + 1;                                // BQ == BK

    const float* qg  = q + ((size_t)bh * Sn + q0) * Dh;
    const float* kg  = k + (size_t)bh * Sn * Dh;
    const float* vg  = v + (size_t)bh * Sn * Dh;
    const float* amg = am + (size_t)b * Sn;
    const float  hmv = hm[h];

    // ---- load Q tile (hi only, pre-scaled by log2e) ----
    load_hi_scaled(qg, smem + SM_QHI, tid);

    // per-lane ldmatrix base addresses
    const int m0 = wid * 16;
    const uint32_t qoff = sbase + SM_QHI + (m0 + (lane & 15)) * RSB + ((lane >> 4) & 1) * 16;
    const uint32_t koff = sbase + SM_KHI + ((lane & 7) + ((lane >> 4) & 1) * 8) * RSB + ((lane >> 3) & 1) * 16;
    const uint32_t voff = sbase + SM_VHI + ((lane & 7) + ((lane >> 3) & 1) * 8) * RSB + ((lane >> 4) & 1) * 16;
    constexpr int DKL = SM_KLO - SM_KHI;
    constexpr int DVL = SM_VLO - SM_VHI;

    float o[64];
    #pragma unroll
    for (int i = 0; i < 64; ++i) o[i] = 0.0f;
    float M0 = -INFINITY, M1 = -INFINITY, L0 = 0.0f, L1 = 0.0f;

    const int rg0 = q0 + m0 + (lane >> 2);   // global q row (upper)
    const int rg1 = rg0 + 8;
    const int c00 = 2 * (lane & 3);          // local col base within n8 tile

    for (int kt = 0; kt < nkt; ++kt) {
        __syncthreads();
        load_split(kg + (size_t)kt * BK * Dh, smem + SM_KHI, smem + SM_KLO, tid);
        load_split(vg + (size_t)kt * BK * Dh, smem + SM_VHI, smem + SM_VLO, tid);
        if (tid < BK) am_s[tid] = amg[kt * BK + tid] * LOG2E;
        __syncthreads();

        // ---- S' = log2e * Q K^T (2-pass: Qhi*Khi + Qhi*Klo), 16x64 per warp ----
        float sv[32];
        #pragma unroll
        for (int i = 0; i < 32; ++i) sv[i] = 0.0f;
        #pragma unroll
        for (int t = 0; t < 8; ++t) {                 // k16 tiles over d=128
            uint32_t ah[4];
            ldsm4(ah, qoff + t * 32);
            #pragma unroll
            for (int g = 0; g < 4; ++g) {             // n16 groups over 64 cols
                uint32_t bh4[4], bl4[4];
                ldsm4(bh4, koff + g * (16 * RSB) + t * 32);
                ldsm4(bl4, koff + DKL + g * (16 * RSB) + t * 32);
                mma_f16(sv + 8 * g,     ah, bh4);
                mma_f16(sv + 8 * g + 4, ah, bh4 + 2);
                mma_f16(sv + 8 * g,     ah, bl4);
                mma_f16(sv + 8 * g + 4, ah, bl4 + 2);
            }
        }

        // ---- causal mask + additive attn_mask (log2 domain) ----
        float amr[16];
        #pragma unroll
        for (int n = 0; n < 8; ++n) {
            float2 a2 = *reinterpret_cast<const float2*>(&am_s[8 * n + c00]);
            amr[2 * n] = a2.x; amr[2 * n + 1] = a2.y;
        }
        if (kt == nkt - 1) {   // only the diagonal tile needs element checks
            #pragma unroll
            for (int n = 0; n < 8; ++n) {
                int cg = kt * BK + 8 * n + c00;
                sv[4*n+0] = (cg     <= rg0) ? sv[4*n+0] + amr[2*n]   : -1e30f;
                sv[4*n+1] = (cg + 1 <= rg0) ? sv[4*n+1] + amr[2*n+1] : -1e30f;
                sv[4*n+2] = (cg     <= rg1) ? sv[4*n+2] + amr[2*n]   : -1e30f;
                sv[4*n+3] = (cg + 1 <= rg1) ? sv[4*n+3] + amr[2*n+1] : -1e30f;
            }
        } else {
            #pragma unroll
            for (int n = 0; n < 8; ++n) {
                sv[4*n+0] += amr[2*n];   sv[4*n+1] += amr[2*n+1];
                sv[4*n+2] += amr[2*n];   sv[4*n+3] += amr[2*n+1];
            }
        }

        // ---- online softmax in base-2 domain (MUFU ex2) ----
        float t0 = -INFINITY, t1 = -INFINITY;
        #pragma unroll
        for (int n = 0; n < 8; ++n) {
            t0 = fmaxf(t0, fmaxf(sv[4*n+0], sv[4*n+1]));
            t1 = fmaxf(t1, fmaxf(sv[4*n+2], sv[4*n+3]));
        }
        t0 = fmaxf(t0, __shfl_xor_sync(0xffffffffu, t0, 1));
        t0 = fmaxf(t0, __shfl_xor_sync(0xffffffffu, t0, 2));
        t1 = fmaxf(t1, __shfl_xor_sync(0xffffffffu, t1, 1));
        t1 = fmaxf(t1, __shfl_xor_sync(0xffffffffu, t1, 2));
        float M0n = fmaxf(M0, t0), M1n = fmaxf(M1, t1);
        float a0 = ex2f(M0 - M0n), a1 = ex2f(M1 - M1n);
        M0 = M0n; M1 = M1n;

        float l0 = 0.0f, l1 = 0.0f;
        #pragma unroll
        for (int n = 0; n < 8; ++n) {
            sv[4*n+0] = ex2f(sv[4*n+0] - M0n);
            sv[4*n+1] = ex2f(sv[4*n+1] - M0n);
            l0 += sv[4*n+0] + sv[4*n+1];
            sv[4*n+2] = ex2f(sv[4*n+2] - M1n);
            sv[4*n+3] = ex2f(sv[4*n+3] - M1n);
            l1 += sv[4*n+2] + sv[4*n+3];
        }
        l0 += __shfl_xor_sync(0xffffffffu, l0, 1);
        l0 += __shfl_xor_sync(0xffffffffu, l0, 2);
        l1 += __shfl_xor_sync(0xffffffffu, l1, 1);
        l1 += __shfl_xor_sync(0xffffffffu, l1, 2);
        L0 = L0 * a0 + l0;
        L1 = L1 * a1 + l1;
        #pragma unroll
        for (int n = 0; n < 16; ++n) {
            o[4*n+0] *= a0; o[4*n+1] *= a0;
            o[4*n+2] *= a1; o[4*n+3] *= a1;
        }

        // ---- P -> fp16 A-fragments (hi only) ----
        uint32_t ph[4][4];
        #pragma unroll
        for (int t = 0; t < 4; ++t)
            #pragma unroll
            for (int rix = 0; rix < 4; ++rix)
                ph[t][rix] = cvt2h(sv[8*t + 2*rix], sv[8*t + 2*rix + 1]);

        // ---- O += P V (2-pass: Phi*Vhi + Phi*Vlo), 16x128 per warp ----
        #pragma unroll
        for (int t = 0; t < 4; ++t) {                 // k16 tiles over BK=64
            #pragma unroll
            for (int g = 0; g < 8; ++g) {             // n16 groups over d=128
                uint32_t vh4[4], vl4[4];
                ldsm4t(vh4, voff + t * (16 * RSB) + g * 32);
                ldsm4t(vl4, voff + DVL + t * (16 * RSB) + g * 32);
                mma_f16(o + 8 * g,     ph[t], vh4);
                mma_f16(o + 8 * g + 4, ph[t], vh4 + 2);
                mma_f16(o + 8 * g,     ph[t], vl4);
                mma_f16(o + 8 * g + 4, ph[t], vl4 + 2);
            }
        }
    }

    // ---- epilogue: normalize, head_mask, store ----
    float li0 = hmv / L0, li1 = hmv / L1;
    float* o0 = out + ((size_t)bh * Sn + rg0) * Dh;
    float* o1 = o0 + 8 * Dh;
    #pragma unroll
    for (int n = 0; n < 16; ++n) {
        int c = 8 * n + c00;
        *reinterpret_cast<float2*>(o0 + c) = make_float2(o[4*n+0] * li0, o[4*n+1] * li0);
        *reinterpret_cast<float2*>(o1 + c) = make_float2(o[4*n+2] * li1, o[4*n+3] * li1);
    }
}

// ===================== launch =====================
extern "C" void kernel_launch(void* const* d_in, const int* in_sizes, int n_in,
                              void* d_out, int out_size)
{
    const float* q  = (const float*)d_in[0];
    const float* k  = (const float*)d_in[1];
    const float* v  = (const float*)d_in[2];
    const float* am = (const float*)d_in[3];
    const float* hm = (const float*)d_in[4];
    float* out = (float*)d_out;

    cudaFuncSetAttribute(fa_mma_kernel,
                         cudaFuncAttributeMaxDynamicSharedMemorySize, SM_TOTAL);

    dim3 grid(Sn / BQ, Bsz * Hn);   // (32 q-tiles, 32 bh)
    fa_mma_kernel<<<grid, NT, SM_TOTAL>>>(q, k, v, am, hm, out);
}

// round 8
// speedup vs baseline: 1.4107x; 1.1234x over previous
#include <cuda_runtime.h>
#include <cuda_fp16.h>
#include <cstdint>
#include <math.h>

// ===================== problem constants =====================
constexpr int Bsz = 2;
constexpr int Hn  = 16;
constexpr int Sn  = 2048;
constexpr int Dh  = 128;

constexpr int BQ = 64;    // q rows per CTA (4 warps x 16 rows)
constexpr int BK = 64;    // k cols per iteration
constexpr int NT = 128;   // 4 warps
constexpr int NTILES = Sn / 64;   // 32 tiles of 64 rows
constexpr int NBH = Bsz * Hn;     // 32

constexpr int RSB = 272;  // row stride in bytes (136 fp16) -> conflict-free ldmatrix
constexpr int TILE1 = 64 * RSB;       // one 64x128 fp16 tile, padded: 17408 B
constexpr int TILEB = 2 * TILE1;      // hi + lo pair: 34816 B

// smem byte offsets (hi tile at base, lo tile at +TILE1)
constexpr int SM_Q  = 0;
constexpr int SM_K  = SM_Q + TILEB;    // 34816
constexpr int SM_V  = SM_K + TILEB;    // 69632
constexpr int SM_AM = SM_V + TILEB;    // 104448
constexpr int SM_TOTAL = SM_AM + BK * 4;  // 104704 B (x2 CTAs = 209.4KB/SM)

constexpr float LOG2E = 1.4426950408889634f;

// ===================== device scratch (converted tiles, padded layout) =====================
__device__ __align__(16) unsigned char g_q[NBH][NTILES][TILEB];
__device__ __align__(16) unsigned char g_k[NBH][NTILES][TILEB];
__device__ __align__(16) unsigned char g_v[NBH][NTILES][TILEB];

// ===================== helpers =====================
static __device__ __forceinline__ uint32_t smem_u32(const void* p) {
    uint32_t a;
    asm("{ .reg .u64 t; cvta.to.shared.u64 t, %1; cvt.u32.u64 %0, t; }" : "=r"(a) : "l"(p));
    return a;
}
static __device__ __forceinline__ void ldsm4(uint32_t* r, uint32_t a) {
    asm volatile("ldmatrix.sync.aligned.m8n8.x4.shared.b16 {%0,%1,%2,%3}, [%4];"
                 : "=r"(r[0]), "=r"(r[1]), "=r"(r[2]), "=r"(r[3]) : "r"(a));
}
static __device__ __forceinline__ void ldsm4t(uint32_t* r, uint32_t a) {
    asm volatile("ldmatrix.sync.aligned.m8n8.x4.trans.shared.b16 {%0,%1,%2,%3}, [%4];"
                 : "=r"(r[0]), "=r"(r[1]), "=r"(r[2]), "=r"(r[3]) : "r"(a));
}
static __device__ __forceinline__ void mma_f16(float* c, const uint32_t* a, const uint32_t* b) {
    asm volatile("mma.sync.aligned.m16n8k16.row.col.f32.f16.f16.f32 "
                 "{%0,%1,%2,%3},{%4,%5,%6,%7},{%8,%9},{%0,%1,%2,%3};"
                 : "+f"(c[0]), "+f"(c[1]), "+f"(c[2]), "+f"(c[3])
                 : "r"(a[0]), "r"(a[1]), "r"(a[2]), "r"(a[3]), "r"(b[0]), "r"(b[1]));
}
static __device__ __forceinline__ uint32_t cvt2h(float lo, float hi) {
    uint32_t r;
    asm("cvt.rn.f16x2.f32 %0, %1, %2;" : "=r"(r) : "f"(hi), "f"(lo));
    return r;
}
static __device__ __forceinline__ float2 h2f2(uint32_t u) {
    __half2 h = *reinterpret_cast<__half2*>(&u);
    return __half22float2(h);
}
static __device__ __forceinline__ float ex2f(float x) {
    float r;
    asm("ex2.approx.ftz.f32 %0, %1;" : "=f"(r) : "f"(x));
    return r;
}

#define CP16(s, g) \
    asm volatile("cp.async.cg.shared.global [%0], [%1], 16;" :: "r"(s), "l"(g) : "memory")
#define CP_COMMIT() asm volatile("cp.async.commit_group;" ::: "memory")
#define CP_WAIT0()  asm volatile("cp.async.wait_group 0;"  ::: "memory")

// async copy a full hi+lo tile pair (34816 B) gmem->smem; 17 chunks/thread
static __device__ __forceinline__ void copy_tile_async(uint32_t sdst,
                                                       const unsigned char* gsrc, int tid) {
    unsigned long long ga = (unsigned long long)__cvta_generic_to_global((void*)gsrc);
    #pragma unroll
    for (int it = 0; it < 17; ++it) {
        int c = (it * NT + tid) * 16;
        CP16(sdst + c, ga + c);
    }
}

// ===================== prepass: fp32 -> fp16 hi/lo tiles in padded layout =====================
template <bool SCALE>
static __device__ __forceinline__ void conv_tile(const float* __restrict__ g,
                                                 unsigned char* dst, int tid) {
    #pragma unroll
    for (int it = 0; it < 8; ++it) {
        int e = it * 128 + tid;                // 1024 chunks of 8 floats
        int row = e >> 4, c8 = e & 15;
        const float4* src = reinterpret_cast<const float4*>(g) + 2 * e;
        float4 x = src[0], y = src[1];
        if (SCALE) {
            x.x *= LOG2E; x.y *= LOG2E; x.z *= LOG2E; x.w *= LOG2E;
            y.x *= LOG2E; y.y *= LOG2E; y.z *= LOG2E; y.w *= LOG2E;
        }
        uint32_t h0 = cvt2h(x.x, x.y), h1 = cvt2h(x.z, x.w);
        uint32_t h2 = cvt2h(y.x, y.y), h3 = cvt2h(y.z, y.w);
        float2 f0 = h2f2(h0), f1 = h2f2(h1), f2 = h2f2(h2), f3 = h2f2(h3);
        uint32_t l0 = cvt2h(x.x - f0.x, x.y - f0.y);
        uint32_t l1 = cvt2h(x.z - f1.x, x.w - f1.y);
        uint32_t l2 = cvt2h(y.x - f2.x, y.y - f2.y);
        uint32_t l3 = cvt2h(y.z - f3.x, y.w - f3.y);
        int off = row * RSB + c8 * 16;
        *reinterpret_cast<uint4*>(dst + off)         = make_uint4(h0, h1, h2, h3);
        *reinterpret_cast<uint4*>(dst + TILE1 + off) = make_uint4(l0, l1, l2, l3);
    }
}

__global__ __launch_bounds__(128)
void prep_kernel(const float* __restrict__ q, const float* __restrict__ k,
                 const float* __restrict__ v)
{
    const int kt = blockIdx.x, bh = blockIdx.y, tid = threadIdx.x;
    const size_t base = ((size_t)bh * Sn + (size_t)kt * 64) * Dh;
    conv_tile<true >(q + base, &g_q[bh][kt][0], tid);
    conv_tile<false>(k + base, &g_k[bh][kt][0], tid);
    conv_tile<false>(v + base, &g_v[bh][kt][0], tid);
}

// ===================== main kernel =====================
__global__ __launch_bounds__(NT, 2)
void fa_mma_kernel(const float* __restrict__ am, const float* __restrict__ hm,
                   float* __restrict__ out)
{
    extern __shared__ char smem[];
    const uint32_t sbase = smem_u32(smem);
    float* am_s = reinterpret_cast<float*>(smem + SM_AM);

    const int tid = threadIdx.x, wid = tid >> 5, lane = tid & 31;
    const int bh = blockIdx.y, b = bh >> 4, h = bh & 15;
    const int qt = (int)gridDim.x - 1 - (int)blockIdx.x;   // heavy tiles first
    const int q0 = qt * BQ;
    const int nkt = qt + 1;                                // BQ == BK

    const float* amg = am + (size_t)b * Sn;
    const float  hmv = hm[h];

    // ---- async-load Q tile (hi+lo, pre-scaled) ----
    copy_tile_async(sbase + SM_Q, &g_q[bh][qt][0], tid);
    CP_COMMIT();

    // per-lane ldmatrix base addresses
    const int m0 = wid * 16;
    const uint32_t qoff = sbase + SM_Q + (m0 + (lane & 15)) * RSB + ((lane >> 4) & 1) * 16;
    const uint32_t koff = sbase + SM_K + ((lane & 7) + ((lane >> 4) & 1) * 8) * RSB + ((lane >> 3) & 1) * 16;
    const uint32_t voff = sbase + SM_V + ((lane & 7) + ((lane >> 3) & 1) * 8) * RSB + ((lane >> 4) & 1) * 16;

    float o[64];
    #pragma unroll
    for (int i = 0; i < 64; ++i) o[i] = 0.0f;
    float M0 = -INFINITY, M1 = -INFINITY, L0 = 0.0f, L1 = 0.0f;

    const int rg0 = q0 + m0 + (lane >> 2);   // global q row (upper)
    const int rg1 = rg0 + 8;
    const int c00 = 2 * (lane & 3);          // local col base within n8 tile

    for (int kt = 0; kt < nkt; ++kt) {
        __syncthreads();                      // prev iteration consumers done
        copy_tile_async(sbase + SM_K, &g_k[bh][kt][0], tid);
        copy_tile_async(sbase + SM_V, &g_v[bh][kt][0], tid);
        CP_COMMIT();
        if (tid < BK) am_s[tid] = amg[kt * BK + tid] * LOG2E;
        CP_WAIT0();
        __syncthreads();

        // ---- S' = log2e * Q K^T (3-pass: Qhi*Khi + Qhi*Klo + Qlo*Khi) ----
        float sv[32];
        #pragma unroll
        for (int i = 0; i < 32; ++i) sv[i] = 0.0f;
        #pragma unroll
        for (int t = 0; t < 8; ++t) {                 // k16 tiles over d=128
            uint32_t ah[4], al[4];
            ldsm4(ah, qoff + t * 32);
            ldsm4(al, qoff + TILE1 + t * 32);
            #pragma unroll
            for (int g = 0; g < 4; ++g) {             // n16 groups over 64 cols
                uint32_t bh4[4], bl4[4];
                ldsm4(bh4, koff + g * (16 * RSB) + t * 32);
                ldsm4(bl4, koff + TILE1 + g * (16 * RSB) + t * 32);
                mma_f16(sv + 8 * g,     ah, bh4);
                mma_f16(sv + 8 * g + 4, ah, bh4 + 2);
                mma_f16(sv + 8 * g,     ah, bl4);
                mma_f16(sv + 8 * g + 4, ah, bl4 + 2);
                mma_f16(sv + 8 * g,     al, bh4);
                mma_f16(sv + 8 * g + 4, al, bh4 + 2);
            }
        }

        // ---- causal mask + additive attn_mask (log2 domain) ----
        float amr[16];
        #pragma unroll
        for (int n = 0; n < 8; ++n) {
            float2 a2 = *reinterpret_cast<const float2*>(&am_s[8 * n + c00]);
            amr[2 * n] = a2.x; amr[2 * n + 1] = a2.y;
        }
        if (kt == nkt - 1) {   // only the diagonal tile needs element checks
            #pragma unroll
            for (int n = 0; n < 8; ++n) {
                int cg = kt * BK + 8 * n + c00;
                sv[4*n+0] = (cg     <= rg0) ? sv[4*n+0] + amr[2*n]   : -1e30f;
                sv[4*n+1] = (cg + 1 <= rg0) ? sv[4*n+1] + amr[2*n+1] : -1e30f;
                sv[4*n+2] = (cg     <= rg1) ? sv[4*n+2] + amr[2*n]   : -1e30f;
                sv[4*n+3] = (cg + 1 <= rg1) ? sv[4*n+3] + amr[2*n+1] : -1e30f;
            }
        } else {
            #pragma unroll
            for (int n = 0; n < 8; ++n) {
                sv[4*n+0] += amr[2*n];   sv[4*n+1] += amr[2*n+1];
                sv[4*n+2] += amr[2*n];   sv[4*n+3] += amr[2*n+1];
            }
        }

        // ---- online softmax in base-2 domain (MUFU ex2) ----
        float t0 = -INFINITY, t1 = -INFINITY;
        #pragma unroll
        for (int n = 0; n < 8; ++n) {
            t0 = fmaxf(t0, fmaxf(sv[4*n+0], sv[4*n+1]));
            t1 = fmaxf(t1, fmaxf(sv[4*n+2], sv[4*n+3]));
        }
        t0 = fmaxf(t0, __shfl_xor_sync(0xffffffffu, t0, 1));
        t0 = fmaxf(t0, __shfl_xor_sync(0xffffffffu, t0, 2));
        t1 = fmaxf(t1, __shfl_xor_sync(0xffffffffu, t1, 1));
        t1 = fmaxf(t1, __shfl_xor_sync(0xffffffffu, t1, 2));
        float M0n = fmaxf(M0, t0), M1n = fmaxf(M1, t1);
        float a0 = ex2f(M0 - M0n), a1 = ex2f(M1 - M1n);
        M0 = M0n; M1 = M1n;

        float l0 = 0.0f, l1 = 0.0f;
        #pragma unroll
        for (int n = 0; n < 8; ++n) {
            sv[4*n+0] = ex2f(sv[4*n+0] - M0n);
            sv[4*n+1] = ex2f(sv[4*n+1] - M0n);
            l0 += sv[4*n+0] + sv[4*n+1];
            sv[4*n+2] = ex2f(sv[4*n+2] - M1n);
            sv[4*n+3] = ex2f(sv[4*n+3] - M1n);
            l1 += sv[4*n+2] + sv[4*n+3];
        }
        l0 += __shfl_xor_sync(0xffffffffu, l0, 1);
        l0 += __shfl_xor_sync(0xffffffffu, l0, 2);
        l1 += __shfl_xor_sync(0xffffffffu, l1, 1);
        l1 += __shfl_xor_sync(0xffffffffu, l1, 2);
        L0 = L0 * a0 + l0;
        L1 = L1 * a1 + l1;
        #pragma unroll
        for (int n = 0; n < 16; ++n) {
            o[4*n+0] *= a0; o[4*n+1] *= a0;
            o[4*n+2] *= a1; o[4*n+3] *= a1;
        }

        // ---- P -> fp16 A-fragments (hi only) ----
        uint32_t ph[4][4];
        #pragma unroll
        for (int t = 0; t < 4; ++t)
            #pragma unroll
            for (int rix = 0; rix < 4; ++rix)
                ph[t][rix] = cvt2h(sv[8*t + 2*rix], sv[8*t + 2*rix + 1]);

        // ---- O += P V (2-pass: Phi*Vhi + Phi*Vlo), 16x128 per warp ----
        #pragma unroll
        for (int t = 0; t < 4; ++t) {                 // k16 tiles over BK=64
            #pragma unroll
            for (int g = 0; g < 8; ++g) {             // n16 groups over d=128
                uint32_t vh4[4], vl4[4];
                ldsm4t(vh4, voff + t * (16 * RSB) + g * 32);
                ldsm4t(vl4, voff + TILE1 + t * (16 * RSB) + g * 32);
                mma_f16(o + 8 * g,     ph[t], vh4);
                mma_f16(o + 8 * g + 4, ph[t], vh4 + 2);
                mma_f16(o + 8 * g,     ph[t], vl4);
                mma_f16(o + 8 * g + 4, ph[t], vl4 + 2);
            }
        }
    }

    // ---- epilogue: normalize, head_mask, store ----
    float li0 = hmv / L0, li1 = hmv / L1;
    float* o0 = out + ((size_t)bh * Sn + rg0) * Dh;
    float* o1 = o0 + 8 * Dh;
    #pragma unroll
    for (int n = 0; n < 16; ++n) {
        int c = 8 * n + c00;
        *reinterpret_cast<float2*>(o0 + c) = make_float2(o[4*n+0] * li0, o[4*n+1] * li0);
        *reinterpret_cast<float2*>(o1 + c) = make_float2(o[4*n+2] * li1, o[4*n+3] * li1);
    }
}

// ===================== launch =====================
extern "C" void kernel_launch(void* const* d_in, const int* in_sizes, int n_in,
                              void* d_out, int out_size)
{
    const float* q  = (const float*)d_in[0];
    const float* k  = (const float*)d_in[1];
    const float* v  = (const float*)d_in[2];
    const float* am = (const float*)d_in[3];
    const float* hm = (const float*)d_in[4];
    float* out = (float*)d_out;

    cudaFuncSetAttribute(fa_mma_kernel,
                         cudaFuncAttributeMaxDynamicSharedMemorySize, SM_TOTAL);

    prep_kernel<<<dim3(NTILES, NBH), 128>>>(q, k, v);
    dim3 grid(Sn / BQ, NBH);   // (32 q-tiles, 32 bh)
    fa_mma_kernel<<<grid, NT, SM_TOTAL>>>(am, hm, out);
}